// round 10
// baseline (speedup 1.0000x reference)
#include <cuda_runtime.h>
#include <cuda_fp16.h>

#define N_NODES 50000
#define N_EDGES 800000
#define HID     128
#define NHEAD   2
#define CH      64
#define G_GRAPHS 64
#define IN_DIM  4
#define OUT_DIM 7
#define NEG_SLOPE 0.2f
#define BN_EPS 1e-5f

// ---------------- scratch (device globals; no runtime allocation) ------------
__device__ __half g_xlh[N_NODES * HID];      // source-side transform (fp16)
__device__ float g_xr[N_NODES * HID];        // target-side transform (fp32)
__device__ float g_acc1[N_NODES * HID];      // layer-1 output h1 (pre-BN)
__device__ float g_acc2[N_NODES * HID];      // layer-2 output h2 (pre-BN)
__device__ int   g_deg[N_NODES];             // in-degree histogram
__device__ int   g_rowptr[N_NODES + 1];      // CSR row pointers (by dst)
__device__ int   g_cursor[N_NODES];          // fill cursors
__device__ int   g_csr_src[N_EDGES];         // CSR: src node per edge
__device__ float g_sums[HID];                // BN channel sums
__device__ float g_sumsq[HID];               // BN channel sum of squares
__device__ float g_bn_sc[HID];               // BN scale
__device__ float g_bn_sh[HID];               // BN shift
__device__ float g_pooled[G_GRAPHS * HID];
__device__ float g_cnt[G_GRAPHS];

#define FMA2(d, a, b, c) \
    asm("fma.rn.f32x2 %0, %1, %2, %3;" : "=l"(d) : "l"(a), "l"(b), "l"(c))

union F2U { unsigned long long u; float2 f; };

// ---------------- layer-1 transform + zero-init of small state ---------------
__global__ void k_transform1(const float* __restrict__ x,
                             const float* __restrict__ Wl,
                             const float* __restrict__ Wr) {
    int c = threadIdx.x; // 128
    float wl0 = Wl[0 * HID + c], wl1 = Wl[1 * HID + c];
    float wl2 = Wl[2 * HID + c], wl3 = Wl[3 * HID + c];
    float wr0 = Wr[0 * HID + c], wr1 = Wr[1 * HID + c];
    float wr2 = Wr[2 * HID + c], wr3 = Wr[3 * HID + c];
    for (int n = blockIdx.x; n < N_NODES; n += gridDim.x) {
        float x0 = x[n * IN_DIM + 0];
        float x1 = x[n * IN_DIM + 1];
        float x2 = x[n * IN_DIM + 2];
        float x3 = x[n * IN_DIM + 3];
        float xlv = x0 * wl0 + x1 * wl1 + x2 * wl2 + x3 * wl3;
        g_xlh[n * HID + c] = __float2half(xlv);
        g_xr[n * HID + c] = x0 * wr0 + x1 * wr1 + x2 * wr2 + x3 * wr3;
        if (c == 0) g_deg[n] = 0;
        if (c == 1) g_cursor[n] = 0;
    }
    if (blockIdx.x == 0) {
        g_sums[c] = 0.f; g_sumsq[c] = 0.f;
        for (int i = c; i < G_GRAPHS * HID; i += HID) g_pooled[i] = 0.f;
        if (c < G_GRAPHS) g_cnt[c] = 0.f;
    }
}

// ---------------- CSR build: histogram ----------------------------------------
__global__ void k_hist(const int* __restrict__ ei) {
    int stride = gridDim.x * blockDim.x;
    for (int e = blockIdx.x * blockDim.x + threadIdx.x; e < N_EDGES; e += stride)
        atomicAdd(&g_deg[ei[N_EDGES + e]], 1);
}

// ---------------- CSR build: foolproof single-block scan ----------------------
__global__ void k_scan() {
    __shared__ int s_part[1024];
    const int CHUNK = 49;   // 1024 * 49 = 50176 >= N_NODES
    int t = threadIdx.x;
    int lo = t * CHUNK;
    int hi = lo + CHUNK; if (hi > N_NODES) hi = N_NODES;
    int sum = 0;
    for (int i = lo; i < hi; i++) sum += g_deg[i];
    s_part[t] = sum;
    __syncthreads();
    if (t == 0) {
        int acc = 0;
        for (int k = 0; k < 1024; k++) {
            int v = s_part[k];
            s_part[k] = acc;
            acc += v;
        }
        g_rowptr[N_NODES] = acc;
    }
    __syncthreads();
    int run = s_part[t];
    for (int i = lo; i < hi; i++) {
        g_rowptr[i] = run;
        run += g_deg[i];
    }
}

// ---------------- CSR build: fill ----------------------------------------------
__global__ void k_fill(const int* __restrict__ ei) {
    int stride = gridDim.x * blockDim.x;
    for (int e = blockIdx.x * blockDim.x + threadIdx.x; e < N_EDGES; e += stride) {
        int s = ei[e];
        int d = ei[N_EDGES + e];
        int pos = atomicAdd(&g_cursor[d], 1);
        g_csr_src[g_rowptr[d] + pos] = s;
    }
}

// ---------------- fused GATv2 edge pass: 8 ch/lane, 2 edges/warp-iter ---------
// One warp per destination node. Lane layout: lh = lane&15 covers channels
// lh*8..lh*8+7 (lh 0-7 = head0, 8-15 = head1); half = lane>>4 picks even/odd
// logical edge t. t=0 is the self loop, t>=1 are CSR in-edges. Trip counts
// padded so all 32 lanes stay convergent (full-mask shfl safe). Head score
// reduced by a 3-step butterfly within 8-lane groups; each lane's exp IS its
// head's p, so weighted accumulation needs no cross-head exchange. Halves
// merge once per node via shfl_xor(...,16). Softmax max-shift skipped
// (scores O(1)): identical alpha after normalization.
__global__ void k_edge_csr(const float* __restrict__ att,
                           const float* __restrict__ bias, int layer) {
    __shared__ float sm_s[8 * 128];
    __shared__ float sm_q[8 * 128];
    float* out = layer ? g_acc2 : g_acc1;
    int lane = threadIdx.x & 31;
    int wib = threadIdx.x >> 5;
    int node = blockIdx.x * 8 + wib;   // grid is exactly N_NODES/8 blocks
    int lh = lane & 15;
    int half = lane >> 4;
    int co = lh * 8;                   // 8 channels per lane

    // per-lane 8 channels of att and xr
    float att8[8], xr8[8];
    {
        float4 a0 = *(const float4*)&att[co];
        float4 a1 = *(const float4*)&att[co + 4];
        att8[0]=a0.x; att8[1]=a0.y; att8[2]=a0.z; att8[3]=a0.w;
        att8[4]=a1.x; att8[5]=a1.y; att8[6]=a1.z; att8[7]=a1.w;
        float4 r0 = *(const float4*)&g_xr[node * HID + co];
        float4 r1 = *(const float4*)&g_xr[node * HID + co + 4];
        xr8[0]=r0.x; xr8[1]=r0.y; xr8[2]=r0.z; xr8[3]=r0.w;
        xr8[4]=r1.x; xr8[5]=r1.y; xr8[6]=r1.z; xr8[7]=r1.w;
    }

    float acc[8];
    #pragma unroll
    for (int k = 0; k < 8; k++) acc[k] = 0.f;
    float denom = 0.f;

    int beg = g_rowptr[node];
    int T = (g_rowptr[node + 1] - beg) + 1;   // +1 for self loop at t=0
    int Tpad = (T + 1) & ~1;

    for (int t = half; t < Tpad; t += 2) {
        bool valid = (t < T);
        int s = node;
        if (valid && t > 0) s = g_csr_src[beg + t - 1];

        uint4 r = *(const uint4*)&g_xlh[s * HID + co];
        __half2 h0 = *(__half2*)&r.x;
        __half2 h1 = *(__half2*)&r.y;
        __half2 h2 = *(__half2*)&r.z;
        __half2 h3 = *(__half2*)&r.w;
        float2 f0 = __half22float2(h0);
        float2 f1 = __half22float2(h1);
        float2 f2 = __half22float2(h2);
        float2 f3 = __half22float2(h3);
        float a8[8] = { f0.x, f0.y, f1.x, f1.y, f2.x, f2.y, f3.x, f3.y };

        float part = 0.f;
        #pragma unroll
        for (int k = 0; k < 8; k++) {
            float m = a8[k] + xr8[k];
            m = m > 0.f ? m : NEG_SLOPE * m;
            part = fmaf(m, att8[k], part);
        }
        // reduce within 8-lane group (one head of one edge)
        part += __shfl_xor_sync(0xffffffffu, part, 4);
        part += __shfl_xor_sync(0xffffffffu, part, 2);
        part += __shfl_xor_sync(0xffffffffu, part, 1);

        float p = valid ? __expf(part) : 0.f;
        #pragma unroll
        for (int k = 0; k < 8; k++)
            acc[k] = fmaf(p, a8[k], acc[k]);
        denom += p;
    }

    // merge the two halves (same channel mapping, same head groups)
    denom += __shfl_xor_sync(0xffffffffu, denom, 16);
    #pragma unroll
    for (int k = 0; k < 8; k++)
        acc[k] += __shfl_xor_sync(0xffffffffu, acc[k], 16);

    if (half == 0) {
        float inv = __fdividef(1.f, denom);
        float4 b0 = *(const float4*)&bias[co];
        float4 b1 = *(const float4*)&bias[co + 4];
        float v[8];
        v[0] = fmaf(acc[0], inv, b0.x);
        v[1] = fmaf(acc[1], inv, b0.y);
        v[2] = fmaf(acc[2], inv, b0.z);
        v[3] = fmaf(acc[3], inv, b0.w);
        v[4] = fmaf(acc[4], inv, b1.x);
        v[5] = fmaf(acc[5], inv, b1.y);
        v[6] = fmaf(acc[6], inv, b1.z);
        v[7] = fmaf(acc[7], inv, b1.w);
        *(float4*)&out[node * HID + co]     = make_float4(v[0], v[1], v[2], v[3]);
        *(float4*)&out[node * HID + co + 4] = make_float4(v[4], v[5], v[6], v[7]);
        #pragma unroll
        for (int k = 0; k < 8; k++) {
            sm_s[wib * 128 + co + k] = v[k];
            sm_q[wib * 128 + co + k] = v[k] * v[k];
        }
    }
    __syncthreads();
    if (threadIdx.x < 128) {
        int c = threadIdx.x;
        float s = 0.f, q = 0.f;
        #pragma unroll
        for (int t = 0; t < 8; t++) {
            s += sm_s[t * 128 + c];
            q += sm_q[t * 128 + c];
        }
        atomicAdd(&g_sums[c], s);
        atomicAdd(&g_sumsq[c], q);
    }
}

// ---------------- BN prep: compute scale/shift, re-zero stats ----------------
__global__ void k_bn_prep(const float* __restrict__ gamma,
                          const float* __restrict__ beta) {
    int c = threadIdx.x; // 128
    const float invN = 1.f / (float)N_NODES;
    float mu  = g_sums[c] * invN;
    float var = g_sumsq[c] * invN - mu * mu;
    float sc  = gamma[c] * rsqrtf(var + BN_EPS);
    g_bn_sc[c] = sc;
    g_bn_sh[c] = beta[c] - mu * sc;
    g_sums[c] = 0.f;
    g_sumsq[c] = 0.f;
}

// ---------------- layer-2 transforms with fused BN1+ReLU on the A load -------
// [g_xlh | g_xr] = relu(bn(g_acc1)) @ [Wl2 | Wr2]; xl half written as fp16.
__global__ void k_gemm2(const float* __restrict__ Wl,
                        const float* __restrict__ Wr) {
    __shared__ __align__(16) float sA[32][68];    // [k][row], padded
    __shared__ __align__(16) float wTd[32][256];  // [k][col duplicated pairs]

    int tid = threadIdx.x;
    int row0 = blockIdx.x * 64;
    const float* W = blockIdx.y ? Wr : Wl;

    int cg = tid & 31;   // 32 col groups of 4
    int rg = tid >> 5;   // 8 row groups of 8
    int c0 = cg * 4;
    int rg8 = rg * 8;

    unsigned long long acc[4][4];
    #pragma unroll
    for (int i = 0; i < 4; i++)
        #pragma unroll
        for (int j = 0; j < 4; j++) acc[i][j] = 0ull;

    for (int k0 = 0; k0 < HID; k0 += 32) {
        #pragma unroll
        for (int half = 0; half < 2; half++) {
            int u = tid + half * 256;
            int r = u >> 3;             // 0..63
            int k4 = (u & 7) * 4;
            int row = row0 + r;
            int rr = row < N_NODES ? row : N_NODES - 1;
            float4 v = *(const float4*)&g_acc1[rr * HID + k0 + k4];
            float4 sc = *(const float4*)&g_bn_sc[k0 + k4];
            float4 sh = *(const float4*)&g_bn_sh[k0 + k4];
            float t0 = fmaf(v.x, sc.x, sh.x); t0 = t0 > 0.f ? t0 : 0.f;
            float t1 = fmaf(v.y, sc.y, sh.y); t1 = t1 > 0.f ? t1 : 0.f;
            float t2 = fmaf(v.z, sc.z, sh.z); t2 = t2 > 0.f ? t2 : 0.f;
            float t3 = fmaf(v.w, sc.w, sh.w); t3 = t3 > 0.f ? t3 : 0.f;
            sA[k4 + 0][r] = t0;
            sA[k4 + 1][r] = t1;
            sA[k4 + 2][r] = t2;
            sA[k4 + 3][r] = t3;
        }
        #pragma unroll
        for (int i = 0; i < 4; i++) {
            int u = tid + i * 256;
            int kk = u >> 5;
            int c4 = (u & 31) * 4;
            float4 w = *(const float4*)&W[(k0 + kk) * HID + c4];
            *(float4*)&wTd[kk][c4 * 2]     = make_float4(w.x, w.x, w.y, w.y);
            *(float4*)&wTd[kk][c4 * 2 + 4] = make_float4(w.z, w.z, w.w, w.w);
        }
        __syncthreads();
        #pragma unroll
        for (int kk = 0; kk < 32; kk++) {
            ulonglong2 A0 = *(ulonglong2*)&sA[kk][rg8];
            ulonglong2 A1 = *(ulonglong2*)&sA[kk][rg8 + 4];
            ulonglong2 B0 = *(ulonglong2*)&wTd[kk][c0 * 2];
            ulonglong2 B1 = *(ulonglong2*)&wTd[kk][c0 * 2 + 4];
            FMA2(acc[0][0], A0.x, B0.x, acc[0][0]);
            FMA2(acc[0][1], A0.x, B0.y, acc[0][1]);
            FMA2(acc[0][2], A0.x, B1.x, acc[0][2]);
            FMA2(acc[0][3], A0.x, B1.y, acc[0][3]);
            FMA2(acc[1][0], A0.y, B0.x, acc[1][0]);
            FMA2(acc[1][1], A0.y, B0.y, acc[1][1]);
            FMA2(acc[1][2], A0.y, B1.x, acc[1][2]);
            FMA2(acc[1][3], A0.y, B1.y, acc[1][3]);
            FMA2(acc[2][0], A1.x, B0.x, acc[2][0]);
            FMA2(acc[2][1], A1.x, B0.y, acc[2][1]);
            FMA2(acc[2][2], A1.x, B1.x, acc[2][2]);
            FMA2(acc[2][3], A1.x, B1.y, acc[2][3]);
            FMA2(acc[3][0], A1.y, B0.x, acc[3][0]);
            FMA2(acc[3][1], A1.y, B0.y, acc[3][1]);
            FMA2(acc[3][2], A1.y, B1.x, acc[3][2]);
            FMA2(acc[3][3], A1.y, B1.y, acc[3][3]);
        }
        __syncthreads();
    }

    #pragma unroll
    for (int rp = 0; rp < 4; rp++) {
        F2U p0, p1, p2, p3;
        p0.u = acc[rp][0]; p1.u = acc[rp][1];
        p2.u = acc[rp][2]; p3.u = acc[rp][3];
        int row_e = row0 + rg8 + rp * 2;
        if (blockIdx.y == 0) {
            if (row_e < N_NODES) {
                __half2 ha = __floats2half2_rn(p0.f.x, p1.f.x);
                __half2 hb = __floats2half2_rn(p2.f.x, p3.f.x);
                uint2 pk;
                pk.x = *(unsigned int*)&ha;
                pk.y = *(unsigned int*)&hb;
                *(uint2*)&g_xlh[row_e * HID + c0] = pk;
            }
            if (row_e + 1 < N_NODES) {
                __half2 ha = __floats2half2_rn(p0.f.y, p1.f.y);
                __half2 hb = __floats2half2_rn(p2.f.y, p3.f.y);
                uint2 pk;
                pk.x = *(unsigned int*)&ha;
                pk.y = *(unsigned int*)&hb;
                *(uint2*)&g_xlh[(row_e + 1) * HID + c0] = pk;
            }
        } else {
            if (row_e < N_NODES)
                *(float4*)&g_xr[row_e * HID + c0] =
                    make_float4(p0.f.x, p1.f.x, p2.f.x, p3.f.x);
            if (row_e + 1 < N_NODES)
                *(float4*)&g_xr[(row_e + 1) * HID + c0] =
                    make_float4(p0.f.y, p1.f.y, p2.f.y, p3.f.y);
        }
    }
}

// ---------------- global mean pool with fused BN2 + ReLU ---------------------
__global__ void k_pool(const int* __restrict__ batch) {
    int gwarp = (blockIdx.x * blockDim.x + threadIdx.x) >> 5;
    int nwarps = (gridDim.x * blockDim.x) >> 5;
    int lane = threadIdx.x & 31;
    float4 sc = *(const float4*)&g_bn_sc[lane * 4];
    float4 sh = *(const float4*)&g_bn_sh[lane * 4];
    for (int n = gwarp; n < N_NODES; n += nwarps) {
        int g = __ldg(&batch[n]);
        float4 v = *(const float4*)&g_acc2[n * HID + lane * 4];
        float v0 = fmaf(v.x, sc.x, sh.x); v0 = v0 > 0.f ? v0 : 0.f;
        float v1 = fmaf(v.y, sc.y, sh.y); v1 = v1 > 0.f ? v1 : 0.f;
        float v2 = fmaf(v.z, sc.z, sh.z); v2 = v2 > 0.f ? v2 : 0.f;
        float v3 = fmaf(v.w, sc.w, sh.w); v3 = v3 > 0.f ? v3 : 0.f;
        float* dptr = &g_pooled[g * HID + lane * 4];
        asm volatile("red.global.add.v4.f32 [%0], {%1,%2,%3,%4};"
                     :: "l"(dptr), "f"(v0), "f"(v1), "f"(v2), "f"(v3)
                     : "memory");
        if (lane == 0) atomicAdd(&g_cnt[g], 1.f);
    }
}

// ---------------- MLP head ----------------------------------------------------
__global__ void k_head(const float* __restrict__ W3, const float* __restrict__ b3,
                       const float* __restrict__ W4, const float* __restrict__ b4,
                       float* __restrict__ out) {
    __shared__ float z[CH];
    int g = blockIdx.x;   // 64 graphs
    int t = threadIdx.x;  // 64 threads
    float cnt = g_cnt[g];
    float inv = 1.f / (cnt > 1.f ? cnt : 1.f);
    float a = b3[t];
    #pragma unroll 4
    for (int k = 0; k < HID; k++)
        a += (g_pooled[g * HID + k] * inv) * W3[k * CH + t];
    z[t] = a > 0.f ? a : 0.f;
    __syncthreads();
    if (t < OUT_DIM) {
        float o = b4[t];
        #pragma unroll
        for (int k = 0; k < CH; k++)
            o += z[k] * W4[k * OUT_DIM + t];
        out[g * OUT_DIM + t] = o;
    }
}

// ---------------- launch ------------------------------------------------------
extern "C" void kernel_launch(void* const* d_in, const int* in_sizes, int n_in,
                              void* d_out, int out_size) {
    const float* x     = (const float*)d_in[0];
    const int*   ei    = (const int*)d_in[1];    // int32 (JAX x64 disabled)
    const int*   batch = (const int*)d_in[2];
    const float* Wl1 = (const float*)d_in[3];
    const float* Wr1 = (const float*)d_in[4];
    const float* att1= (const float*)d_in[5];
    const float* b1  = (const float*)d_in[6];
    const float* g1  = (const float*)d_in[7];
    const float* be1 = (const float*)d_in[8];
    const float* Wl2 = (const float*)d_in[9];
    const float* Wr2 = (const float*)d_in[10];
    const float* att2= (const float*)d_in[11];
    const float* b2  = (const float*)d_in[12];
    const float* g2  = (const float*)d_in[13];
    const float* be2 = (const float*)d_in[14];
    const float* W3  = (const float*)d_in[15];
    const float* b3  = (const float*)d_in[16];
    const float* W4  = (const float*)d_in[17];
    const float* b4  = (const float*)d_in[18];
    float* out = (float*)d_out;

    // ---- transforms + CSR build (CSR shared by both layers) ----
    k_transform1<<<2048, 128>>>(x, Wl1, Wr1);
    k_hist<<<1600, 512>>>(ei);
    k_scan<<<1, 1024>>>();
    k_fill<<<1600, 512>>>(ei);

    // ---- layer 1 (fully fused edge pass) ----
    k_edge_csr<<<N_NODES / 8, 256>>>(att1, b1, 0);
    k_bn_prep<<<1, 128>>>(g1, be1);

    // ---- layer 2 transforms (BN1+ReLU fused into A load; xl written fp16) ----
    dim3 ggrid((N_NODES + 63) / 64, 2);
    k_gemm2<<<ggrid, 256>>>(Wl2, Wr2);

    // ---- layer 2 ----
    k_edge_csr<<<N_NODES / 8, 256>>>(att2, b2, 1);
    k_bn_prep<<<1, 128>>>(g2, be2);

    // ---- pool + head (BN2+ReLU fused into pool) ----
    k_pool<<<512, 256>>>(batch);
    k_head<<<G_GRAPHS, CH>>>(W3, b3, W4, b4, out);
}

// round 12
// speedup vs baseline: 1.0507x; 1.0507x over previous
#include <cuda_runtime.h>
#include <cuda_fp16.h>

#define N_NODES 50000
#define N_EDGES 800000
#define HID     128
#define NHEAD   2
#define CH      64
#define G_GRAPHS 64
#define IN_DIM  4
#define OUT_DIM 7
#define NEG_SLOPE 0.2f
#define BN_EPS 1e-5f

// ---------------- scratch (device globals; no runtime allocation) ------------
__device__ __half g_xlh[N_NODES * HID];      // source-side transform (fp16)
__device__ float g_xr[N_NODES * HID];        // target-side transform (fp32)
__device__ float g_acc1[N_NODES * HID];      // layer-1 output h1 (pre-BN)
__device__ float g_acc2[N_NODES * HID];      // layer-2 output h2 (pre-BN)
__device__ int   g_deg[N_NODES];             // in-degree histogram
__device__ int   g_rowptr[N_NODES + 1];      // CSR row pointers (by dst)
__device__ int   g_cursor[N_NODES];          // fill cursors
__device__ int   g_csr_src[N_EDGES];         // CSR: src node per edge
__device__ float g_sums[HID];                // BN channel sums
__device__ float g_sumsq[HID];               // BN channel sum of squares
__device__ float g_bn_sc[HID];               // BN scale
__device__ float g_bn_sh[HID];               // BN shift
__device__ float g_pooled[G_GRAPHS * HID];
__device__ float g_cnt[G_GRAPHS];

#define FMA2(d, a, b, c) \
    asm("fma.rn.f32x2 %0, %1, %2, %3;" : "=l"(d) : "l"(a), "l"(b), "l"(c))

union F2U { unsigned long long u; float2 f; };

// load 4 fp16 xl channels -> float4
__device__ __forceinline__ float4 load_xlh4(int node, int co) {
    uint2 r = *(const uint2*)&g_xlh[node * HID + co];
    __half2 h0 = *(__half2*)&r.x;
    __half2 h1 = *(__half2*)&r.y;
    float2 f0 = __half22float2(h0);
    float2 f1 = __half22float2(h1);
    return make_float4(f0.x, f0.y, f1.x, f1.y);
}

// ---------------- init: zero deg/cursor/stats (covers ALL nodes) -------------
__global__ void k_init() {
    int stride = gridDim.x * blockDim.x;
    for (int i = blockIdx.x * blockDim.x + threadIdx.x; i < N_NODES; i += stride) {
        g_deg[i] = 0;
        g_cursor[i] = 0;
        if (i < HID) { g_sums[i] = 0.f; g_sumsq[i] = 0.f; }
        if (i < G_GRAPHS * HID) g_pooled[i] = 0.f;
        if (i < G_GRAPHS) g_cnt[i] = 0.f;
    }
}

// ---------------- fused layer-1 transform + degree histogram -----------------
// Blocks [0, TBLOCKS) do the transform; blocks [TBLOCKS, TBLOCKS+HBLOCKS) do
// the in-degree histogram. Independent work, overlapped in one launch.
#define TBLOCKS 2048
#define HBLOCKS 1024
__global__ void k_transform_hist(const float* __restrict__ x,
                                 const float* __restrict__ Wl,
                                 const float* __restrict__ Wr,
                                 const int* __restrict__ ei) {
    if (blockIdx.x < TBLOCKS) {
        int c = threadIdx.x; // 128
        float wl0 = Wl[0 * HID + c], wl1 = Wl[1 * HID + c];
        float wl2 = Wl[2 * HID + c], wl3 = Wl[3 * HID + c];
        float wr0 = Wr[0 * HID + c], wr1 = Wr[1 * HID + c];
        float wr2 = Wr[2 * HID + c], wr3 = Wr[3 * HID + c];
        for (int n = blockIdx.x; n < N_NODES; n += TBLOCKS) {
            float x0 = x[n * IN_DIM + 0];
            float x1 = x[n * IN_DIM + 1];
            float x2 = x[n * IN_DIM + 2];
            float x3 = x[n * IN_DIM + 3];
            float xlv = x0 * wl0 + x1 * wl1 + x2 * wl2 + x3 * wl3;
            g_xlh[n * HID + c] = __float2half(xlv);
            g_xr[n * HID + c] = x0 * wr0 + x1 * wr1 + x2 * wr2 + x3 * wr3;
        }
    } else {
        int tid = (blockIdx.x - TBLOCKS) * blockDim.x + threadIdx.x;
        int stride = HBLOCKS * blockDim.x;
        for (int e = tid; e < N_EDGES; e += stride)
            atomicAdd(&g_deg[ei[N_EDGES + e]], 1);
    }
}

// ---------------- CSR build: parallel single-block scan ----------------------
// Per-thread chunk sums -> 1024-wide Hillis-Steele scan -> prefix writeback.
__global__ void k_scan() {
    __shared__ int s[1024];
    const int CHUNK = 49;   // 1024 * 49 = 50176 >= N_NODES
    int t = threadIdx.x;
    int lo = t * CHUNK;
    int hi = lo + CHUNK; if (hi > N_NODES) hi = N_NODES;
    int sum = 0;
    for (int i = lo; i < hi; i++) sum += g_deg[i];
    s[t] = sum;
    __syncthreads();
    // Hillis-Steele inclusive scan over the 1024 partials
    #pragma unroll
    for (int off = 1; off < 1024; off <<= 1) {
        int v = 0;
        if (t >= off) v = s[t - off];
        __syncthreads();
        s[t] += v;
        __syncthreads();
    }
    if (t == 1023) g_rowptr[N_NODES] = s[1023];
    int run = (t > 0) ? s[t - 1] : 0;   // exclusive prefix of this chunk
    for (int i = lo; i < hi; i++) {
        g_rowptr[i] = run;
        run += g_deg[i];
    }
}

// ---------------- CSR build: fill ----------------------------------------------
__global__ void k_fill(const int* __restrict__ ei) {
    int stride = gridDim.x * blockDim.x;
    for (int e = blockIdx.x * blockDim.x + threadIdx.x; e < N_EDGES; e += stride) {
        int s = ei[e];
        int d = ei[N_EDGES + e];
        int pos = atomicAdd(&g_cursor[d], 1);
        g_csr_src[g_rowptr[d] + pos] = s;
    }
}

// ---------------- fused GATv2 edge pass, CSR form (R6 structure, fp16 xl) ----
// One warp per destination node. Lanes hold 4 channels each (ch = lane*4+k);
// lanes 0-15 = head 0, 16-31 = head 1. Softmax max-shift skipped (scores O(1)):
// identical alpha after normalization.
__global__ void k_edge_csr(const float* __restrict__ att,
                           const float* __restrict__ bias, int layer) {
    __shared__ float sm_s[8 * 128];
    __shared__ float sm_q[8 * 128];
    float* out = layer ? g_acc2 : g_acc1;
    int lane = threadIdx.x & 31;
    int wib = threadIdx.x >> 5;
    int node = blockIdx.x * 8 + wib;   // grid is exactly N_NODES/8 blocks
    int co = lane * 4;

    float4 w = *(const float4*)&att[co];
    float4 b = *(const float4*)&g_xr[node * HID + co];
    float ax = 0.f, ay = 0.f, az = 0.f, aw = 0.f;
    float denom = 0.f;

#define PROCESS(a)                                                              \
    {                                                                           \
        float m0 = a.x + b.x, m1 = a.y + b.y, m2 = a.z + b.z, m3 = a.w + b.w;   \
        m0 = m0 > 0.f ? m0 : NEG_SLOPE * m0;                                    \
        m1 = m1 > 0.f ? m1 : NEG_SLOPE * m1;                                    \
        m2 = m2 > 0.f ? m2 : NEG_SLOPE * m2;                                    \
        m3 = m3 > 0.f ? m3 : NEG_SLOPE * m3;                                    \
        float part = m0 * w.x + m1 * w.y + m2 * w.z + m3 * w.w;                 \
        part += __shfl_xor_sync(0xffffffffu, part, 8);                          \
        part += __shfl_xor_sync(0xffffffffu, part, 4);                          \
        part += __shfl_xor_sync(0xffffffffu, part, 2);                          \
        part += __shfl_xor_sync(0xffffffffu, part, 1);                          \
        float p = __expf(part);                                                 \
        ax = fmaf(p, a.x, ax); ay = fmaf(p, a.y, ay);                           \
        az = fmaf(p, a.z, az); aw = fmaf(p, a.w, aw);                           \
        denom += p;                                                             \
    }

    // self loop
    {
        float4 a = load_xlh4(node, co);
        PROCESS(a);
    }

    int beg = g_rowptr[node];
    int end = g_rowptr[node + 1];
    float4 a_n = make_float4(0.f, 0.f, 0.f, 0.f);
    if (beg < end) {
        int s = g_csr_src[beg];
        a_n = load_xlh4(s, co);
    }
    for (int j = beg; j < end; j++) {
        float4 a = a_n;
        if (j + 1 < end) {
            int s = g_csr_src[j + 1];
            a_n = load_xlh4(s, co);
        }
        PROCESS(a);
    }
#undef PROCESS

    float inv = __fdividef(1.f, denom);
    float4 bi = *(const float4*)&bias[co];
    float v0 = fmaf(ax, inv, bi.x);
    float v1 = fmaf(ay, inv, bi.y);
    float v2 = fmaf(az, inv, bi.z);
    float v3 = fmaf(aw, inv, bi.w);
    *(float4*)&out[node * HID + co] = make_float4(v0, v1, v2, v3);

    // BN stats: per-warp values -> block reduce -> global atomics
    sm_s[wib * 128 + co + 0] = v0;  sm_q[wib * 128 + co + 0] = v0 * v0;
    sm_s[wib * 128 + co + 1] = v1;  sm_q[wib * 128 + co + 1] = v1 * v1;
    sm_s[wib * 128 + co + 2] = v2;  sm_q[wib * 128 + co + 2] = v2 * v2;
    sm_s[wib * 128 + co + 3] = v3;  sm_q[wib * 128 + co + 3] = v3 * v3;
    __syncthreads();
    if (threadIdx.x < 128) {
        int c = threadIdx.x;
        float s = 0.f, q = 0.f;
        #pragma unroll
        for (int t = 0; t < 8; t++) {
            s += sm_s[t * 128 + c];
            q += sm_q[t * 128 + c];
        }
        atomicAdd(&g_sums[c], s);
        atomicAdd(&g_sumsq[c], q);
    }
}

// ---------------- BN prep: compute scale/shift, re-zero stats ----------------
__global__ void k_bn_prep(const float* __restrict__ gamma,
                          const float* __restrict__ beta) {
    int c = threadIdx.x; // 128
    const float invN = 1.f / (float)N_NODES;
    float mu  = g_sums[c] * invN;
    float var = g_sumsq[c] * invN - mu * mu;
    float sc  = gamma[c] * rsqrtf(var + BN_EPS);
    g_bn_sc[c] = sc;
    g_bn_sh[c] = beta[c] - mu * sc;
    g_sums[c] = 0.f;
    g_sumsq[c] = 0.f;
}

// ---------------- layer-2 transforms with fused BN1+ReLU on the A load -------
// [g_xlh | g_xr] = relu(bn(g_acc1)) @ [Wl2 | Wr2]; xl half written as fp16.
__global__ void k_gemm2(const float* __restrict__ Wl,
                        const float* __restrict__ Wr) {
    __shared__ __align__(16) float sA[32][68];    // [k][row], padded
    __shared__ __align__(16) float wTd[32][256];  // [k][col duplicated pairs]

    int tid = threadIdx.x;
    int row0 = blockIdx.x * 64;
    const float* W = blockIdx.y ? Wr : Wl;

    int cg = tid & 31;   // 32 col groups of 4
    int rg = tid >> 5;   // 8 row groups of 8
    int c0 = cg * 4;
    int rg8 = rg * 8;

    unsigned long long acc[4][4];
    #pragma unroll
    for (int i = 0; i < 4; i++)
        #pragma unroll
        for (int j = 0; j < 4; j++) acc[i][j] = 0ull;

    for (int k0 = 0; k0 < HID; k0 += 32) {
        #pragma unroll
        for (int half = 0; half < 2; half++) {
            int u = tid + half * 256;
            int r = u >> 3;             // 0..63
            int k4 = (u & 7) * 4;
            int row = row0 + r;
            int rr = row < N_NODES ? row : N_NODES - 1;
            float4 v = *(const float4*)&g_acc1[rr * HID + k0 + k4];
            float4 sc = *(const float4*)&g_bn_sc[k0 + k4];
            float4 sh = *(const float4*)&g_bn_sh[k0 + k4];
            float t0 = fmaf(v.x, sc.x, sh.x); t0 = t0 > 0.f ? t0 : 0.f;
            float t1 = fmaf(v.y, sc.y, sh.y); t1 = t1 > 0.f ? t1 : 0.f;
            float t2 = fmaf(v.z, sc.z, sh.z); t2 = t2 > 0.f ? t2 : 0.f;
            float t3 = fmaf(v.w, sc.w, sh.w); t3 = t3 > 0.f ? t3 : 0.f;
            sA[k4 + 0][r] = t0;
            sA[k4 + 1][r] = t1;
            sA[k4 + 2][r] = t2;
            sA[k4 + 3][r] = t3;
        }
        #pragma unroll
        for (int i = 0; i < 4; i++) {
            int u = tid + i * 256;
            int kk = u >> 5;
            int c4 = (u & 31) * 4;
            float4 w = *(const float4*)&W[(k0 + kk) * HID + c4];
            *(float4*)&wTd[kk][c4 * 2]     = make_float4(w.x, w.x, w.y, w.y);
            *(float4*)&wTd[kk][c4 * 2 + 4] = make_float4(w.z, w.z, w.w, w.w);
        }
        __syncthreads();
        #pragma unroll
        for (int kk = 0; kk < 32; kk++) {
            ulonglong2 A0 = *(ulonglong2*)&sA[kk][rg8];
            ulonglong2 A1 = *(ulonglong2*)&sA[kk][rg8 + 4];
            ulonglong2 B0 = *(ulonglong2*)&wTd[kk][c0 * 2];
            ulonglong2 B1 = *(ulonglong2*)&wTd[kk][c0 * 2 + 4];
            FMA2(acc[0][0], A0.x, B0.x, acc[0][0]);
            FMA2(acc[0][1], A0.x, B0.y, acc[0][1]);
            FMA2(acc[0][2], A0.x, B1.x, acc[0][2]);
            FMA2(acc[0][3], A0.x, B1.y, acc[0][3]);
            FMA2(acc[1][0], A0.y, B0.x, acc[1][0]);
            FMA2(acc[1][1], A0.y, B0.y, acc[1][1]);
            FMA2(acc[1][2], A0.y, B1.x, acc[1][2]);
            FMA2(acc[1][3], A0.y, B1.y, acc[1][3]);
            FMA2(acc[2][0], A1.x, B0.x, acc[2][0]);
            FMA2(acc[2][1], A1.x, B0.y, acc[2][1]);
            FMA2(acc[2][2], A1.x, B1.x, acc[2][2]);
            FMA2(acc[2][3], A1.x, B1.y, acc[2][3]);
            FMA2(acc[3][0], A1.y, B0.x, acc[3][0]);
            FMA2(acc[3][1], A1.y, B0.y, acc[3][1]);
            FMA2(acc[3][2], A1.y, B1.x, acc[3][2]);
            FMA2(acc[3][3], A1.y, B1.y, acc[3][3]);
        }
        __syncthreads();
    }

    #pragma unroll
    for (int rp = 0; rp < 4; rp++) {
        F2U p0, p1, p2, p3;
        p0.u = acc[rp][0]; p1.u = acc[rp][1];
        p2.u = acc[rp][2]; p3.u = acc[rp][3];
        int row_e = row0 + rg8 + rp * 2;
        if (blockIdx.y == 0) {
            if (row_e < N_NODES) {
                __half2 ha = __floats2half2_rn(p0.f.x, p1.f.x);
                __half2 hb = __floats2half2_rn(p2.f.x, p3.f.x);
                uint2 pk;
                pk.x = *(unsigned int*)&ha;
                pk.y = *(unsigned int*)&hb;
                *(uint2*)&g_xlh[row_e * HID + c0] = pk;
            }
            if (row_e + 1 < N_NODES) {
                __half2 ha = __floats2half2_rn(p0.f.y, p1.f.y);
                __half2 hb = __floats2half2_rn(p2.f.y, p3.f.y);
                uint2 pk;
                pk.x = *(unsigned int*)&ha;
                pk.y = *(unsigned int*)&hb;
                *(uint2*)&g_xlh[(row_e + 1) * HID + c0] = pk;
            }
        } else {
            if (row_e < N_NODES)
                *(float4*)&g_xr[row_e * HID + c0] =
                    make_float4(p0.f.x, p1.f.x, p2.f.x, p3.f.x);
            if (row_e + 1 < N_NODES)
                *(float4*)&g_xr[(row_e + 1) * HID + c0] =
                    make_float4(p0.f.y, p1.f.y, p2.f.y, p3.f.y);
        }
    }
}

// ---------------- global mean pool with fused BN2 + ReLU ---------------------
__global__ void k_pool(const int* __restrict__ batch) {
    int gwarp = (blockIdx.x * blockDim.x + threadIdx.x) >> 5;
    int nwarps = (gridDim.x * blockDim.x) >> 5;
    int lane = threadIdx.x & 31;
    float4 sc = *(const float4*)&g_bn_sc[lane * 4];
    float4 sh = *(const float4*)&g_bn_sh[lane * 4];
    for (int n = gwarp; n < N_NODES; n += nwarps) {
        int g = __ldg(&batch[n]);
        float4 v = *(const float4*)&g_acc2[n * HID + lane * 4];
        float v0 = fmaf(v.x, sc.x, sh.x); v0 = v0 > 0.f ? v0 : 0.f;
        float v1 = fmaf(v.y, sc.y, sh.y); v1 = v1 > 0.f ? v1 : 0.f;
        float v2 = fmaf(v.z, sc.z, sh.z); v2 = v2 > 0.f ? v2 : 0.f;
        float v3 = fmaf(v.w, sc.w, sh.w); v3 = v3 > 0.f ? v3 : 0.f;
        float* dptr = &g_pooled[g * HID + lane * 4];
        asm volatile("red.global.add.v4.f32 [%0], {%1,%2,%3,%4};"
                     :: "l"(dptr), "f"(v0), "f"(v1), "f"(v2), "f"(v3)
                     : "memory");
        if (lane == 0) atomicAdd(&g_cnt[g], 1.f);
    }
}

// ---------------- MLP head ----------------------------------------------------
__global__ void k_head(const float* __restrict__ W3, const float* __restrict__ b3,
                       const float* __restrict__ W4, const float* __restrict__ b4,
                       float* __restrict__ out) {
    __shared__ float z[CH];
    int g = blockIdx.x;   // 64 graphs
    int t = threadIdx.x;  // 64 threads
    float cnt = g_cnt[g];
    float inv = 1.f / (cnt > 1.f ? cnt : 1.f);
    float a = b3[t];
    #pragma unroll 4
    for (int k = 0; k < HID; k++)
        a += (g_pooled[g * HID + k] * inv) * W3[k * CH + t];
    z[t] = a > 0.f ? a : 0.f;
    __syncthreads();
    if (t < OUT_DIM) {
        float o = b4[t];
        #pragma unroll
        for (int k = 0; k < CH; k++)
            o += z[k] * W4[k * OUT_DIM + t];
        out[g * OUT_DIM + t] = o;
    }
}

// ---------------- launch ------------------------------------------------------
extern "C" void kernel_launch(void* const* d_in, const int* in_sizes, int n_in,
                              void* d_out, int out_size) {
    const float* x     = (const float*)d_in[0];
    const int*   ei    = (const int*)d_in[1];    // int32 (JAX x64 disabled)
    const int*   batch = (const int*)d_in[2];
    const float* Wl1 = (const float*)d_in[3];
    const float* Wr1 = (const float*)d_in[4];
    const float* att1= (const float*)d_in[5];
    const float* b1  = (const float*)d_in[6];
    const float* g1  = (const float*)d_in[7];
    const float* be1 = (const float*)d_in[8];
    const float* Wl2 = (const float*)d_in[9];
    const float* Wr2 = (const float*)d_in[10];
    const float* att2= (const float*)d_in[11];
    const float* b2  = (const float*)d_in[12];
    const float* g2  = (const float*)d_in[13];
    const float* be2 = (const float*)d_in[14];
    const float* W3  = (const float*)d_in[15];
    const float* b3  = (const float*)d_in[16];
    const float* W4  = (const float*)d_in[17];
    const float* b4  = (const float*)d_in[18];
    float* out = (float*)d_out;

    // ---- init small state (ALL nodes), fused transform+hist, scan+fill ----
    k_init<<<98, 512>>>();
    k_transform_hist<<<TBLOCKS + HBLOCKS, 128>>>(x, Wl1, Wr1, ei);
    k_scan<<<1, 1024>>>();
    k_fill<<<1600, 512>>>(ei);

    // ---- layer 1 (fully fused edge pass) ----
    k_edge_csr<<<N_NODES / 8, 256>>>(att1, b1, 0);
    k_bn_prep<<<1, 128>>>(g1, be1);

    // ---- layer 2 transforms (BN1+ReLU fused into A load; xl written fp16) ----
    dim3 ggrid((N_NODES + 63) / 64, 2);
    k_gemm2<<<ggrid, 256>>>(Wl2, Wr2);

    // ---- layer 2 ----
    k_edge_csr<<<N_NODES / 8, 256>>>(att2, b2, 1);
    k_bn_prep<<<1, 128>>>(g2, be2);

    // ---- pool + head (BN2+ReLU fused into pool) ----
    k_pool<<<512, 256>>>(batch);
    k_head<<<G_GRAPHS, CH>>>(W3, b3, W4, b4, out);
}

// round 13
// speedup vs baseline: 1.4943x; 1.4222x over previous
#include <cuda_runtime.h>
#include <cuda_fp16.h>
#include <mma.h>
using namespace nvcuda;

#define N_NODES 50000
#define N_PAD   50048    // multiple of 64 for unguarded wmma fragment stores
#define N_EDGES 800000
#define HID     128
#define NHEAD   2
#define CH      64
#define G_GRAPHS 64
#define IN_DIM  4
#define OUT_DIM 7
#define NEG_SLOPE 0.2f
#define BN_EPS 1e-5f

// ---------------- scratch (device globals; no runtime allocation) ------------
__device__ float g_xl[N_PAD * HID];          // source-side transform
__device__ float g_xr[N_PAD * HID];          // target-side transform
__device__ float g_acc1[N_PAD * HID];        // layer-1 output h1 (pre-BN)
__device__ float g_acc2[N_PAD * HID];        // layer-2 output h2 (pre-BN)
__device__ int   g_deg[N_NODES];             // in-degree histogram
__device__ int   g_rowptr[N_NODES + 1];      // CSR row pointers (by dst)
__device__ int   g_cursor[N_NODES];          // fill cursors
__device__ int   g_csr_src[N_EDGES];         // CSR: src node per edge
__device__ float g_sums[HID];                // BN channel sums
__device__ float g_sumsq[HID];               // BN channel sum of squares
__device__ float g_bn_sc[HID];               // BN scale
__device__ float g_bn_sh[HID];               // BN shift
__device__ float g_pooled[G_GRAPHS * HID];
__device__ float g_cnt[G_GRAPHS];

// ---------------- init: zero deg/cursor/stats (covers ALL nodes) -------------
__global__ void k_init() {
    int stride = gridDim.x * blockDim.x;
    for (int i = blockIdx.x * blockDim.x + threadIdx.x; i < N_NODES; i += stride) {
        g_deg[i] = 0;
        g_cursor[i] = 0;
        if (i < HID) { g_sums[i] = 0.f; g_sumsq[i] = 0.f; }
        if (i < G_GRAPHS * HID) g_pooled[i] = 0.f;
        if (i < G_GRAPHS) g_cnt[i] = 0.f;
    }
}

// ---------------- fused layer-1 transform + degree histogram -----------------
#define TBLOCKS 2048
#define HBLOCKS 1024
__global__ void k_transform_hist(const float* __restrict__ x,
                                 const float* __restrict__ Wl,
                                 const float* __restrict__ Wr,
                                 const int* __restrict__ ei) {
    if (blockIdx.x < TBLOCKS) {
        int c = threadIdx.x; // 128
        float wl0 = Wl[0 * HID + c], wl1 = Wl[1 * HID + c];
        float wl2 = Wl[2 * HID + c], wl3 = Wl[3 * HID + c];
        float wr0 = Wr[0 * HID + c], wr1 = Wr[1 * HID + c];
        float wr2 = Wr[2 * HID + c], wr3 = Wr[3 * HID + c];
        for (int n = blockIdx.x; n < N_NODES; n += TBLOCKS) {
            float x0 = x[n * IN_DIM + 0];
            float x1 = x[n * IN_DIM + 1];
            float x2 = x[n * IN_DIM + 2];
            float x3 = x[n * IN_DIM + 3];
            g_xl[n * HID + c] = x0 * wl0 + x1 * wl1 + x2 * wl2 + x3 * wl3;
            g_xr[n * HID + c] = x0 * wr0 + x1 * wr1 + x2 * wr2 + x3 * wr3;
        }
    } else {
        int tid = (blockIdx.x - TBLOCKS) * blockDim.x + threadIdx.x;
        int stride = HBLOCKS * blockDim.x;
        for (int e = tid; e < N_EDGES; e += stride)
            atomicAdd(&g_deg[ei[N_EDGES + e]], 1);
    }
}

// ---------------- CSR build: parallel single-block scan ----------------------
__global__ void k_scan() {
    __shared__ int s[1024];
    const int CHUNK = 49;   // 1024 * 49 = 50176 >= N_NODES
    int t = threadIdx.x;
    int lo = t * CHUNK;
    int hi = lo + CHUNK; if (hi > N_NODES) hi = N_NODES;
    int sum = 0;
    for (int i = lo; i < hi; i++) sum += g_deg[i];
    s[t] = sum;
    __syncthreads();
    #pragma unroll
    for (int off = 1; off < 1024; off <<= 1) {
        int v = 0;
        if (t >= off) v = s[t - off];
        __syncthreads();
        s[t] += v;
        __syncthreads();
    }
    if (t == 1023) g_rowptr[N_NODES] = s[1023];
    int run = (t > 0) ? s[t - 1] : 0;
    for (int i = lo; i < hi; i++) {
        g_rowptr[i] = run;
        run += g_deg[i];
    }
}

// ---------------- CSR build: fill ----------------------------------------------
__global__ void k_fill(const int* __restrict__ ei) {
    int stride = gridDim.x * blockDim.x;
    for (int e = blockIdx.x * blockDim.x + threadIdx.x; e < N_EDGES; e += stride) {
        int s = ei[e];
        int d = ei[N_EDGES + e];
        int pos = atomicAdd(&g_cursor[d], 1);
        g_csr_src[g_rowptr[d] + pos] = s;
    }
}

// ---------------- fused GATv2 edge pass, CSR form (R6 structure, fp32 xl) ----
// One warp per destination node. Lanes hold 4 channels each (ch = lane*4+k);
// lanes 0-15 = head 0, 16-31 = head 1. Softmax max-shift skipped (scores O(1)):
// identical alpha after normalization.
__global__ void k_edge_csr(const float* __restrict__ att,
                           const float* __restrict__ bias, int layer) {
    __shared__ float sm_s[8 * 128];
    __shared__ float sm_q[8 * 128];
    float* out = layer ? g_acc2 : g_acc1;
    int lane = threadIdx.x & 31;
    int wib = threadIdx.x >> 5;
    int node = blockIdx.x * 8 + wib;   // grid is exactly N_NODES/8 blocks
    int co = lane * 4;

    float4 w = *(const float4*)&att[co];
    float4 b = *(const float4*)&g_xr[node * HID + co];
    float ax = 0.f, ay = 0.f, az = 0.f, aw = 0.f;
    float denom = 0.f;

#define PROCESS(a)                                                              \
    {                                                                           \
        float m0 = a.x + b.x, m1 = a.y + b.y, m2 = a.z + b.z, m3 = a.w + b.w;   \
        m0 = m0 > 0.f ? m0 : NEG_SLOPE * m0;                                    \
        m1 = m1 > 0.f ? m1 : NEG_SLOPE * m1;                                    \
        m2 = m2 > 0.f ? m2 : NEG_SLOPE * m2;                                    \
        m3 = m3 > 0.f ? m3 : NEG_SLOPE * m3;                                    \
        float part = m0 * w.x + m1 * w.y + m2 * w.z + m3 * w.w;                 \
        part += __shfl_xor_sync(0xffffffffu, part, 8);                          \
        part += __shfl_xor_sync(0xffffffffu, part, 4);                          \
        part += __shfl_xor_sync(0xffffffffu, part, 2);                          \
        part += __shfl_xor_sync(0xffffffffu, part, 1);                          \
        float p = __expf(part);                                                 \
        ax = fmaf(p, a.x, ax); ay = fmaf(p, a.y, ay);                           \
        az = fmaf(p, a.z, az); aw = fmaf(p, a.w, aw);                           \
        denom += p;                                                             \
    }

    // self loop
    {
        float4 a = *(const float4*)&g_xl[node * HID + co];
        PROCESS(a);
    }

    int beg = g_rowptr[node];
    int end = g_rowptr[node + 1];
    float4 a_n = make_float4(0.f, 0.f, 0.f, 0.f);
    if (beg < end) {
        int s = g_csr_src[beg];
        a_n = *(const float4*)&g_xl[s * HID + co];
    }
    for (int j = beg; j < end; j++) {
        float4 a = a_n;
        if (j + 1 < end) {
            int s = g_csr_src[j + 1];
            a_n = *(const float4*)&g_xl[s * HID + co];
        }
        PROCESS(a);
    }
#undef PROCESS

    float inv = __fdividef(1.f, denom);
    float4 bi = *(const float4*)&bias[co];
    float v0 = fmaf(ax, inv, bi.x);
    float v1 = fmaf(ay, inv, bi.y);
    float v2 = fmaf(az, inv, bi.z);
    float v3 = fmaf(aw, inv, bi.w);
    *(float4*)&out[node * HID + co] = make_float4(v0, v1, v2, v3);

    // BN stats: per-warp values -> block reduce -> global atomics
    sm_s[wib * 128 + co + 0] = v0;  sm_q[wib * 128 + co + 0] = v0 * v0;
    sm_s[wib * 128 + co + 1] = v1;  sm_q[wib * 128 + co + 1] = v1 * v1;
    sm_s[wib * 128 + co + 2] = v2;  sm_q[wib * 128 + co + 2] = v2 * v2;
    sm_s[wib * 128 + co + 3] = v3;  sm_q[wib * 128 + co + 3] = v3 * v3;
    __syncthreads();
    if (threadIdx.x < 128) {
        int c = threadIdx.x;
        float s = 0.f, q = 0.f;
        #pragma unroll
        for (int t = 0; t < 8; t++) {
            s += sm_s[t * 128 + c];
            q += sm_q[t * 128 + c];
        }
        atomicAdd(&g_sums[c], s);
        atomicAdd(&g_sumsq[c], q);
    }
}

// ---------------- BN prep: compute scale/shift, re-zero stats ----------------
__global__ void k_bn_prep(const float* __restrict__ gamma,
                          const float* __restrict__ beta) {
    int c = threadIdx.x; // 128
    const float invN = 1.f / (float)N_NODES;
    float mu  = g_sums[c] * invN;
    float var = g_sumsq[c] * invN - mu * mu;
    float sc  = gamma[c] * rsqrtf(var + BN_EPS);
    g_bn_sc[c] = sc;
    g_bn_sh[c] = beta[c] - mu * sc;
    g_sums[c] = 0.f;
    g_sumsq[c] = 0.f;
}

// ---------------- layer-2 transforms: tensor-core wmma GEMM ------------------
// [g_xl | g_xr] = relu(bn(g_acc1)) @ [Wl2 | Wr2]
// fp16 inputs (converted in smem loads, BN+ReLU fused into A), fp32 accumulate.
// Block 256 thr = 8 warps; tile 64 rows x 128 cols; warp = 16 rows x 64 cols
// (4 wmma 16x16x16 fragments). Buffers padded to N_PAD so fragment stores
// need no bounds checks (pad rows are zero-filled, never read as real nodes).
__global__ void k_gemm2(const float* __restrict__ Wl,
                        const float* __restrict__ Wr) {
    __shared__ __half sA[64][40];     // [row][k], ldm 40 (mult of 8)
    __shared__ __half sB[32][136];    // [k][col], ldm 136 (mult of 8)

    int tid = threadIdx.x;
    int row0 = blockIdx.x * 64;
    const float* W = blockIdx.y ? Wr : Wl;
    float* dst = blockIdx.y ? g_xr : g_xl;
    int wid = tid >> 5;
    int strip = (wid >> 1) << 4;     // 0,16,32,48
    int colb = (wid & 1) << 6;       // 0,64

    wmma::fragment<wmma::accumulator, 16, 16, 16, float> acc[4];
    #pragma unroll
    for (int i = 0; i < 4; i++) wmma::fill_fragment(acc[i], 0.f);

    for (int k0 = 0; k0 < HID; k0 += 32) {
        // ---- A tile: 64x32, BN+ReLU fused, fp32 -> fp16 ----
        #pragma unroll
        for (int i = 0; i < 8; i++) {
            int u = tid + i * 256;
            int r = u >> 5;
            int kk = u & 31;
            float v = g_acc1[(row0 + r) * HID + k0 + kk];
            float t = fmaf(v, g_bn_sc[k0 + kk], g_bn_sh[k0 + kk]);
            t = t > 0.f ? t : 0.f;
            sA[r][kk] = __float2half(t);
        }
        // ---- B tile: 32x128, fp32 -> fp16 ----
        #pragma unroll
        for (int i = 0; i < 16; i++) {
            int u = tid + i * 256;
            int kk = u >> 7;
            int c = u & 127;
            sB[kk][c] = __float2half(W[(k0 + kk) * HID + c]);
        }
        __syncthreads();
        #pragma unroll
        for (int ks = 0; ks < 32; ks += 16) {
            wmma::fragment<wmma::matrix_a, 16, 16, 16, __half, wmma::row_major> fa;
            wmma::load_matrix_sync(fa, &sA[strip][ks], 40);
            #pragma unroll
            for (int n = 0; n < 4; n++) {
                wmma::fragment<wmma::matrix_b, 16, 16, 16, __half, wmma::row_major> fb;
                wmma::load_matrix_sync(fb, &sB[ks][colb + n * 16], 136);
                wmma::mma_sync(acc[n], fa, fb, acc[n]);
            }
        }
        __syncthreads();
    }

    #pragma unroll
    for (int n = 0; n < 4; n++)
        wmma::store_matrix_sync(&dst[(row0 + strip) * HID + colb + n * 16],
                                acc[n], HID, wmma::mem_row_major);
}

// ---------------- global mean pool with fused BN2 + ReLU ---------------------
__global__ void k_pool(const int* __restrict__ batch) {
    int gwarp = (blockIdx.x * blockDim.x + threadIdx.x) >> 5;
    int nwarps = (gridDim.x * blockDim.x) >> 5;
    int lane = threadIdx.x & 31;
    float4 sc = *(const float4*)&g_bn_sc[lane * 4];
    float4 sh = *(const float4*)&g_bn_sh[lane * 4];
    for (int n = gwarp; n < N_NODES; n += nwarps) {
        int g = __ldg(&batch[n]);
        float4 v = *(const float4*)&g_acc2[n * HID + lane * 4];
        float v0 = fmaf(v.x, sc.x, sh.x); v0 = v0 > 0.f ? v0 : 0.f;
        float v1 = fmaf(v.y, sc.y, sh.y); v1 = v1 > 0.f ? v1 : 0.f;
        float v2 = fmaf(v.z, sc.z, sh.z); v2 = v2 > 0.f ? v2 : 0.f;
        float v3 = fmaf(v.w, sc.w, sh.w); v3 = v3 > 0.f ? v3 : 0.f;
        float* dptr = &g_pooled[g * HID + lane * 4];
        asm volatile("red.global.add.v4.f32 [%0], {%1,%2,%3,%4};"
                     :: "l"(dptr), "f"(v0), "f"(v1), "f"(v2), "f"(v3)
                     : "memory");
        if (lane == 0) atomicAdd(&g_cnt[g], 1.f);
    }
}

// ---------------- MLP head ----------------------------------------------------
__global__ void k_head(const float* __restrict__ W3, const float* __restrict__ b3,
                       const float* __restrict__ W4, const float* __restrict__ b4,
                       float* __restrict__ out) {
    __shared__ float z[CH];
    int g = blockIdx.x;   // 64 graphs
    int t = threadIdx.x;  // 64 threads
    float cnt = g_cnt[g];
    float inv = 1.f / (cnt > 1.f ? cnt : 1.f);
    float a = b3[t];
    #pragma unroll 4
    for (int k = 0; k < HID; k++)
        a += (g_pooled[g * HID + k] * inv) * W3[k * CH + t];
    z[t] = a > 0.f ? a : 0.f;
    __syncthreads();
    if (t < OUT_DIM) {
        float o = b4[t];
        #pragma unroll
        for (int k = 0; k < CH; k++)
            o += z[k] * W4[k * OUT_DIM + t];
        out[g * OUT_DIM + t] = o;
    }
}

// ---------------- launch ------------------------------------------------------
extern "C" void kernel_launch(void* const* d_in, const int* in_sizes, int n_in,
                              void* d_out, int out_size) {
    const float* x     = (const float*)d_in[0];
    const int*   ei    = (const int*)d_in[1];    // int32 (JAX x64 disabled)
    const int*   batch = (const int*)d_in[2];
    const float* Wl1 = (const float*)d_in[3];
    const float* Wr1 = (const float*)d_in[4];
    const float* att1= (const float*)d_in[5];
    const float* b1  = (const float*)d_in[6];
    const float* g1  = (const float*)d_in[7];
    const float* be1 = (const float*)d_in[8];
    const float* Wl2 = (const float*)d_in[9];
    const float* Wr2 = (const float*)d_in[10];
    const float* att2= (const float*)d_in[11];
    const float* b2  = (const float*)d_in[12];
    const float* g2  = (const float*)d_in[13];
    const float* be2 = (const float*)d_in[14];
    const float* W3  = (const float*)d_in[15];
    const float* b3  = (const float*)d_in[16];
    const float* W4  = (const float*)d_in[17];
    const float* b4  = (const float*)d_in[18];
    float* out = (float*)d_out;

    // ---- init small state (ALL nodes), fused transform+hist, scan+fill ----
    k_init<<<98, 512>>>();
    k_transform_hist<<<TBLOCKS + HBLOCKS, 128>>>(x, Wl1, Wr1, ei);
    k_scan<<<1, 1024>>>();
    k_fill<<<1600, 512>>>(ei);

    // ---- layer 1 (fully fused edge pass) ----
    k_edge_csr<<<N_NODES / 8, 256>>>(att1, b1, 0);
    k_bn_prep<<<1, 128>>>(g1, be1);

    // ---- layer 2 transforms: tensor-core GEMM (BN1+ReLU fused into A) ----
    dim3 ggrid(N_PAD / 64, 2);
    k_gemm2<<<ggrid, 256>>>(Wl2, Wr2);

    // ---- layer 2 ----
    k_edge_csr<<<N_NODES / 8, 256>>>(att2, b2, 1);
    k_bn_prep<<<1, 128>>>(g2, be2);

    // ---- pool + head (BN2+ReLU fused into pool) ----
    k_pool<<<512, 256>>>(batch);
    k_head<<<G_GRAPHS, CH>>>(W3, b3, W4, b4, out);
}